// round 13
// baseline (speedup 1.0000x reference)
#include <cuda_runtime.h>
#include <cstdint>

// img:  [1, 3, 4096, 4096] float32
// ys,xs: [512] int32
// out:  [256, 6, 32, 32] float32 == linearized [N=512, 3, 32, 32]
//
// One CTA per patch, 128 threads. Descriptor-free async bulk copies:
// threads 0..95 each issue cp.async.bulk (144B, 16B-aligned window covering
// one 32-float patch row) into SMEM; mbarrier expect_tx totals the bytes;
// epilogue does conflict-free LDS + coalesced STG with the 0..3 shift.
// x-wrapping patches (~1%) use the proven coalesced-LDG fallback.

#define H 4096
#define W 4096
#define PH 32
#define PW 32
#define NPATCH 512
#define NROWS 96                   // 3 channels * 32 rows
#define ROW_FLOATS 36              // 16B-aligned copy window covering 32+3 shift
#define ROW_BYTES (ROW_FLOATS * 4) // 144, multiple of 16
#define PATCH_ELEMS 3072
#define TX_TOTAL (NROWS * ROW_BYTES)

__global__ __launch_bounds__(128)
void patch_bulk_kernel(const float* __restrict__ img,
                       const int* __restrict__ ys,
                       const int* __restrict__ xs,
                       float* __restrict__ out)
{
    __shared__ alignas(128) float tile[NROWS * ROW_FLOATS];
    __shared__ alignas(8) unsigned long long mbar;

    const int n = blockIdx.x;
    const int y0 = ys[n];
    const int x0 = xs[n];
    float* __restrict__ out_n = out + (size_t)n * PATCH_ELEMS;
    const int t = threadIdx.x;

    if (x0 <= W - ROW_FLOATS) {
        // ---- async bulk path ----
        const int xa  = x0 & ~3;          // 16B-aligned source start
        const int off = x0 - xa;          // 0..3
        const uint32_t bar = (uint32_t)__cvta_generic_to_shared(&mbar);

        if (t == 0) {
            asm volatile("mbarrier.init.shared.b64 [%0], 1;" :: "r"(bar));
            asm volatile("fence.proxy.async.shared::cta;" ::: "memory");
            asm volatile("mbarrier.arrive.expect_tx.shared.b64 _, [%0], %1;"
                         :: "r"(bar), "r"((uint32_t)TX_TOTAL));
        }
        __syncthreads();

        if (t < NROWS) {
            const int c = t >> 5;         // channel 0..2
            const int r = t & 31;         // row in patch
            int yy = y0 + r; if (yy >= H) yy -= H;
            const float* src = img + ((size_t)c * H + yy) * W + xa;
            const uint32_t dst =
                (uint32_t)__cvta_generic_to_shared(tile + t * ROW_FLOATS);
            asm volatile(
                "cp.async.bulk.shared::cta.global.mbarrier::complete_tx::bytes "
                "[%0], [%1], %2, [%3];"
                :: "r"(dst), "l"(src), "r"((uint32_t)ROW_BYTES), "r"(bar)
                : "memory");
        }

        // all threads wait for the 13824 bytes (phase 0)
        asm volatile(
            "{\n\t"
            ".reg .pred P;\n\t"
            "WAIT_%=:\n\t"
            "mbarrier.try_wait.parity.acquire.cta.shared::cta.b64 P, [%0], 0, 0x989680;\n\t"
            "@P bra DONE_%=;\n\t"
            "bra WAIT_%=;\n\t"
            "DONE_%=:\n\t"
            "}"
            :: "r"(bar) : "memory");

        // epilogue: 3072 elems / 128 threads = 24 each.
        // For fixed k, a warp reads consecutive tile addresses (conflict-free)
        // and writes consecutive out addresses (coalesced).
        #pragma unroll
        for (int k = 0; k < 24; k++) {
            const int e  = t + (k << 7);
            const int j  = e & 31;
            const int rc = e >> 5;        // c*32 + r
            out_n[e] = tile[rc * ROW_FLOATS + off + j];
        }
        return;
    }

    // ---- fallback (~1%): coalesced LDG path, handles x-wrap ----
    const int j = t & 31;
    int xx = x0 + j; if (xx >= W) xx -= W;

    float v[24];
    #pragma unroll
    for (int k = 0; k < 24; k++) {
        const int e = t + (k << 7);
        const int r = (e >> 5) & 31;
        const int c = e >> 10;
        int yy = y0 + r; if (yy >= H) yy -= H;
        v[k] = __ldg(img + ((size_t)c * H + yy) * W + xx);
    }
    #pragma unroll
    for (int k = 0; k < 24; k++) {
        out_n[t + (k << 7)] = v[k];
    }
}

extern "C" void kernel_launch(void* const* d_in, const int* in_sizes, int n_in,
                              void* d_out, int out_size)
{
    const float* img = (const float*)d_in[0];
    const int*   ys  = (const int*)d_in[1];
    const int*   xs  = (const int*)d_in[2];
    float* out = (float*)d_out;

    patch_bulk_kernel<<<NPATCH, 128>>>(img, ys, xs, out);
}

// round 14
// speedup vs baseline: 1.0036x; 1.0036x over previous
#include <cuda_runtime.h>
#include <cstdint>

// img:  [1, 3, 4096, 4096] float32
// ys,xs: [512] int32
// out:  [256, 6, 32, 32] float32 == linearized [N=512, 3, 32, 32]
//
// Dual-engine experiment: one CTA (128 thr) per patch.
//   n even -> cp.async.bulk path (async-copy engine, SMEM staging)
//   n odd  -> front-batched LDG path (L1tex engine)
// If the two ~1.7TB/s ceilings are per-engine, they overlap -> ~4.5us.
// x-wrapping patches always take the LDG path (handles wrap).

#define H 4096
#define W 4096
#define PH 32
#define PW 32
#define NPATCH 512
#define NROWS 96                   // 3 channels * 32 rows
#define ROW_FLOATS 36              // 16B-aligned window covering 32 + shift(0..3)
#define ROW_BYTES (ROW_FLOATS * 4) // 144
#define PATCH_ELEMS 3072
#define TX_TOTAL (NROWS * ROW_BYTES)

__global__ __launch_bounds__(128)
void patch_dual_kernel(const float* __restrict__ img,
                       const int* __restrict__ ys,
                       const int* __restrict__ xs,
                       float* __restrict__ out)
{
    __shared__ alignas(128) float tile[NROWS * ROW_FLOATS];
    __shared__ alignas(8) unsigned long long mbar;

    const int n = blockIdx.x;
    const int y0 = ys[n];
    const int x0 = xs[n];
    float* __restrict__ out_n = out + (size_t)n * PATCH_ELEMS;
    const int t = threadIdx.x;

    const bool bulk_ok = ((n & 1) == 0) && (x0 <= W - ROW_FLOATS);

    if (bulk_ok) {
        // ---- async-bulk path ----
        const int xa  = x0 & ~3;
        const int off = x0 - xa;
        const uint32_t bar = (uint32_t)__cvta_generic_to_shared(&mbar);

        if (t == 0) {
            asm volatile("mbarrier.init.shared.b64 [%0], 1;" :: "r"(bar));
            asm volatile("fence.proxy.async.shared::cta;" ::: "memory");
            asm volatile("mbarrier.arrive.expect_tx.shared.b64 _, [%0], %1;"
                         :: "r"(bar), "r"((uint32_t)TX_TOTAL));
        }
        __syncthreads();

        if (t < NROWS) {
            const int c = t >> 5;
            const int r = t & 31;
            int yy = y0 + r; if (yy >= H) yy -= H;
            const float* src = img + ((size_t)c * H + yy) * W + xa;
            const uint32_t dst =
                (uint32_t)__cvta_generic_to_shared(tile + t * ROW_FLOATS);
            asm volatile(
                "cp.async.bulk.shared::cta.global.mbarrier::complete_tx::bytes "
                "[%0], [%1], %2, [%3];"
                :: "r"(dst), "l"(src), "r"((uint32_t)ROW_BYTES), "r"(bar)
                : "memory");
        }

        asm volatile(
            "{\n\t"
            ".reg .pred P;\n\t"
            "WAIT_%=:\n\t"
            "mbarrier.try_wait.parity.acquire.cta.shared::cta.b64 P, [%0], 0, 0x989680;\n\t"
            "@P bra DONE_%=;\n\t"
            "bra WAIT_%=;\n\t"
            "DONE_%=:\n\t"
            "}"
            :: "r"(bar) : "memory");

        #pragma unroll
        for (int k = 0; k < 24; k++) {
            const int e  = t + (k << 7);
            const int j  = e & 31;
            const int rc = e >> 5;
            out_n[e] = tile[rc * ROW_FLOATS + off + j];
        }
        return;
    }

    // ---- LDG path (odd patches + wrap cases) ----
    const int j = t & 31;
    int xx = x0 + j; if (xx >= W) xx -= W;

    float v[24];
    #pragma unroll
    for (int k = 0; k < 24; k++) {
        const int e = t + (k << 7);
        const int r = (e >> 5) & 31;
        const int c = e >> 10;
        int yy = y0 + r; if (yy >= H) yy -= H;
        v[k] = __ldg(img + ((size_t)c * H + yy) * W + xx);
    }
    #pragma unroll
    for (int k = 0; k < 24; k++) {
        out_n[t + (k << 7)] = v[k];
    }
}

extern "C" void kernel_launch(void* const* d_in, const int* in_sizes, int n_in,
                              void* d_out, int out_size)
{
    const float* img = (const float*)d_in[0];
    const int*   ys  = (const int*)d_in[1];
    const int*   xs  = (const int*)d_in[2];
    float* out = (float*)d_out;

    patch_dual_kernel<<<NPATCH, 128>>>(img, ys, xs, out);
}

// round 15
// speedup vs baseline: 1.3478x; 1.3430x over previous
#include <cuda_runtime.h>

// img:  [1, 3, 4096, 4096] float32
// ys,xs: [512] int32
// out:  [256, 6, 32, 32] float32 == linearized [N=512, 3, 32, 32]
//
// Final-form LDG gather (DRAM-activation-floor bound). Tail-smoothing split:
// one CTA per HALF patch-channel: 512*3*2 = 3072 CTAs x 64 threads.
// lane j = t&31 -> each warp-LDG is one contiguous 128B row slice (coalesced);
// 8 independent front-batched loads per thread; coalesced stores.

#define H 4096
#define W 4096
#define PH 32
#define PW 32
#define NPATCH 512

__global__ __launch_bounds__(64)
void patch_gather_kernel(const float* __restrict__ img,
                         const int* __restrict__ ys,
                         const int* __restrict__ xs,
                         float* __restrict__ out)
{
    const int b    = blockIdx.x;       // 0..3071
    const int pc   = b >> 1;           // patch-channel 0..1535
    const int half = b & 1;            // 0: rows 0..15, 1: rows 16..31
    const int n    = pc / 3;           // patch
    const int c    = pc - n * 3;       // channel

    const int y0 = ys[n];
    const int x0 = xs[n];

    const float* __restrict__ img_c = img + (size_t)c * H * W;
    float* __restrict__ out_nc = out + (size_t)n * (3 * PH * PW) + (size_t)c * (PH * PW);

    // lane j fixed per thread -> warp-LDG = one contiguous 128B row slice
    const int j  = threadIdx.x & 31;
    const int r0 = (half << 4) + (threadIdx.x >> 5);  // base row: half*16 + {0,1}

    int xx = x0 + j; if (xx >= W) xx -= W;

    // 8 independent loads, front-batched (MLP=8/thread)
    float v[8];
    #pragma unroll
    for (int k = 0; k < 8; k++) {
        const int r = r0 + (k << 1);                  // rows r0, r0+2, ..., r0+14
        int yy = y0 + r; if (yy >= H) yy -= H;
        v[k] = __ldg(img_c + (size_t)yy * W + xx);
    }

    #pragma unroll
    for (int k = 0; k < 8; k++) {
        const int r = r0 + (k << 1);
        out_nc[(r << 5) + j] = v[k];
    }
}

extern "C" void kernel_launch(void* const* d_in, const int* in_sizes, int n_in,
                              void* d_out, int out_size)
{
    const float* img = (const float*)d_in[0];
    const int*   ys  = (const int*)d_in[1];
    const int*   xs  = (const int*)d_in[2];
    float* out = (float*)d_out;

    patch_gather_kernel<<<NPATCH * 3 * 2, 64>>>(img, ys, xs, out);
}